// round 13
// baseline (speedup 1.0000x reference)
#include <cuda_runtime.h>
#include <cstdint>
#include <cstddef>

// Problem constants
#define B_ 128
#define T_ 1024
#define D_ 64
#define H_ 256
#define O_ 128

// 128 CTAs = 16 clusters of 8; cluster = row-group (8 batch rows), rank = col-slice
#define NCTA 128
#define CSZ 8
#define BM 8
#define BN 32
#define NTHR 512   // 16 warps; warp w owns k-chunk [16w, 16w+16)

// Dynamic-smem byte offsets
#define OFF_HA0  0u          // h1 state parity 0: [256 k][8 m] f32, 8KB
#define OFF_HA1  8192u
#define OFF_HB0  16384u      // h2 state
#define OFF_HB1  24576u
#define OFF_REDA 32768u      // swizzled reduction scratch, 2048 u64 = 16KB
#define OFF_REDB 49152u
#define SMEM_REQ 102400      // over-request -> 1 CTA/SM guaranteed

// ---------------- device globals (static scratch; no runtime allocation) ----
__device__ float g_xp[(size_t)B_ * T_ * H_];   // Xp[t][b][n] = x@Wx1 + b1
__device__ float g_h2f[B_ * H_];               // final h2(T) for the head

// ---------------- packed f32x2 helpers -------------------------------------
__device__ __forceinline__ void fma2(unsigned long long& acc,
                                     unsigned long long a,
                                     unsigned long long b) {
    asm("fma.rn.f32x2 %0, %1, %2, %0;" : "+l"(acc) : "l"(a), "l"(b));
}
__device__ __forceinline__ void add2(unsigned long long& acc, unsigned long long a) {
    asm("add.rn.f32x2 %0, %0, %1;" : "+l"(acc) : "l"(a));
}
__device__ __forceinline__ unsigned long long dup2(float v) {
    unsigned long long r;
    asm("mov.b64 %0, {%1, %1};" : "=l"(r) : "r"(__float_as_uint(v)));
    return r;
}
__device__ __forceinline__ unsigned long long pack2(float lo, float hi) {
    unsigned long long r;
    asm("mov.b64 %0, {%1, %2};" : "=l"(r) : "r"(__float_as_uint(lo)), "r"(__float_as_uint(hi)));
    return r;
}
__device__ __forceinline__ float lo32(unsigned long long v) {
    return __uint_as_float((unsigned)(v & 0xffffffffull));
}
__device__ __forceinline__ float hi32(unsigned long long v) {
    return __uint_as_float((unsigned)(v >> 32));
}

// ---------------- fast tanh: MUFU ex2 + rcp, ~1e-6 abs error ---------------
__device__ __forceinline__ float fast_tanh(float x) {
    float e, r;
    asm("ex2.approx.f32 %0, %1;" : "=f"(e) : "f"(x * 2.885390081777927f));
    asm("rcp.approx.f32 %0, %1;" : "=f"(r) : "f"(e + 1.0f));
    return fmaf(-2.0f, r, 1.0f);
}

// ---------------- cluster primitives ---------------------------------------
__device__ __forceinline__ uint32_t smem_u32(const void* p) {
    uint32_t a;
    asm("{ .reg .u64 t; cvta.to.shared.u64 t, %1; cvt.u32.u64 %0, t; }" : "=r"(a) : "l"(p));
    return a;
}
__device__ __forceinline__ uint32_t mapa_rank(uint32_t local, uint32_t rank) {
    uint32_t r;
    asm("mapa.shared::cluster.u32 %0, %1, %2;" : "=r"(r) : "r"(local), "r"(rank));
    return r;
}
__device__ __forceinline__ void st_cluster_u64(uint32_t addr, unsigned long long v) {
    asm volatile("st.shared::cluster.u64 [%0], %1;" :: "r"(addr), "l"(v) : "memory");
}
// Fused HW cluster barrier (proven-good in R10): release+acquire, full sync.
#define CLUSTER_SYNC() do { \
    asm volatile("barrier.cluster.arrive.aligned;" ::: "memory"); \
    asm volatile("barrier.cluster.wait.aligned;"   ::: "memory"); } while (0)

// ============================================================================
// Kernel 1: Xp[t][b][:] = x[b][t][:] @ Wx1 + b1   (fully parallel over t)
// ============================================================================
__global__ void __launch_bounds__(256) xproj_kernel(const float* __restrict__ x,
                                                    const float* __restrict__ Wx1,
                                                    const float* __restrict__ b1) {
    extern __shared__ float sm[];
    float* W_s = sm;            // [64][256]  64KB
    float* x_s = sm + D_ * H_;  // [128][64]  32KB
    const int t = blockIdx.x;
    const int tid = threadIdx.x;

    for (int i = tid; i < D_ * H_; i += 256) W_s[i] = Wx1[i];
    for (int i = tid; i < B_ * D_; i += 256) {
        int b = i >> 6, d = i & 63;
        x_s[i] = x[((size_t)b * T_ + t) * D_ + d];
    }
    __syncthreads();

    float wr[D_];
#pragma unroll
    for (int d = 0; d < D_; d++) wr[d] = W_s[d * H_ + tid];
    const float bv = b1[tid];
    float* op = g_xp + (size_t)t * (B_ * H_) + tid;

    for (int b = 0; b < B_; b++) {
        const float4* xr = (const float4*)(x_s + b * D_);
        float a0 = bv, a1 = 0.f, a2 = 0.f, a3 = 0.f;
#pragma unroll
        for (int d4 = 0; d4 < 16; d4 += 4) {
            float4 v0 = xr[d4 + 0], v1 = xr[d4 + 1], v2 = xr[d4 + 2], v3 = xr[d4 + 3];
            a0 += v0.x * wr[4 * d4 + 0]  + v0.y * wr[4 * d4 + 1]
                + v0.z * wr[4 * d4 + 2]  + v0.w * wr[4 * d4 + 3];
            a1 += v1.x * wr[4 * d4 + 4]  + v1.y * wr[4 * d4 + 5]
                + v1.z * wr[4 * d4 + 6]  + v1.w * wr[4 * d4 + 7];
            a2 += v2.x * wr[4 * d4 + 8]  + v2.y * wr[4 * d4 + 9]
                + v2.z * wr[4 * d4 + 10] + v2.w * wr[4 * d4 + 11];
            a3 += v3.x * wr[4 * d4 + 12] + v3.y * wr[4 * d4 + 13]
                + v3.z * wr[4 * d4 + 14] + v3.w * wr[4 * d4 + 15];
        }
        op[(size_t)b * H_] = (a0 + a1) + (a2 + a3);
    }
}

// ============================================================================
// Kernel 2: persistent scan — DSMEM all-gather in 8-CTA clusters.
// R10's proven fused CLUSTER_SYNC (one per phase) + 512 threads (16 warps,
// k-chunk 16/warp) + conflict-free swizzled reduction + shfl-split epilogue.
// Phase p: h1(p+1) = tanh(Xp[p] + h1(p)@Wh1)            [p < T]
//          h2(p)   = tanh(h1(p)@Wx2 + h2(p-1)@Wh2 + b2) [p >= 1]
// ============================================================================
__global__ void __launch_bounds__(NTHR, 1) __cluster_dims__(CSZ, 1, 1)
rnn_main_kernel(const float* __restrict__ Wh1,
                const float* __restrict__ Wx2,
                const float* __restrict__ Wh2,
                const float* __restrict__ b2v) {
    extern __shared__ char smem[];
    const uint32_t sbase = smem_u32(smem);
    unsigned long long* redA = (unsigned long long*)(smem + OFF_REDA);
    unsigned long long* redB = (unsigned long long*)(smem + OFF_REDB);

    const int tid = threadIdx.x;
    const int w = tid >> 5, lane = tid & 31;
    uint32_t rank;
    asm("mov.u32 %0, %%cluster_ctarank;" : "=r"(rank));
    const int mi = blockIdx.x >> 3;
    const int m0 = mi * BM, n0 = (int)rank * BN;

    // Weight slices in registers: warp w covers k in [16w, 16w+16)
    float wh1r[16], wx2r[16], wh2r[16];
    {
        const int col = n0 + lane;
#pragma unroll
        for (int kk = 0; kk < 16; kk++) {
            int k = w * 16 + kk;
            wh1r[kk] = Wh1[k * H_ + col];
            wx2r[kk] = Wx2[k * H_ + col];
            wh2r[kk] = Wh2[k * H_ + col];
        }
    }

    // Zero all four local state buffers (32KB): h1(0)=h2(0)=0 in both parities
    {
        float* s0 = (float*)(smem + OFF_HA0);
        for (int i = tid; i < 8192; i += NTHR) s0[i] = 0.f;
    }

    // Peer smem bases (constant-index unrolled -> registers)
    uint32_t pb[8];
#pragma unroll
    for (int r = 0; r < 8; r++) pb[r] = mapa_rank(sbase, (uint32_t)r);

    // Epilogue mapping: s_t (0=h1,1=h2), output o (p_e=o&3 m-pair, n_e=o>>2
    // column), half (0/1): each of the 2 threads per output reduces 8 of the
    // 16 warp partials; shfl.xor(1) combines.
    const int s_t  = tid >> 8;
    const int rr   = tid & 255;
    const int o    = rr >> 1;
    const int half = rr & 1;            // == lane&1
    const int p_e  = o & 3;
    const int n_e  = o >> 2;
    const int r_off = (m0 + 2 * p_e) * H_ + n0 + n_e;
    const float bias2 = b2v[n0 + n_e];
    const uint32_t soff_full = (uint32_t)((n0 + n_e) * 32 + p_e * 8);

    CLUSTER_SYNC();   // zero-init visible cluster-wide

    for (int p = 0; p <= T_; p++) {
        const int q = p & 1;   // input-buffer parity

        // Prefetch Xp[p] immediately (DRAM latency hides under the GEMM)
        float xv0 = 0.f, xv1 = 0.f;
        if (s_t == 0 && half == 0 && p < T_) {
            const float* xpt = g_xp + (size_t)p * (B_ * H_);
            xv0 = __ldcg(xpt + r_off);
            xv1 = __ldcg(xpt + r_off + H_);
        }

        const float* hAr = (const float*)(smem + (q ? OFF_HA1 : OFF_HA0)) + (w * 16) * 8;
        const float* hBr = (const float*)(smem + (q ? OFF_HB1 : OFF_HB0)) + (w * 16) * 8;

        unsigned long long accA[4] = {0ull, 0ull, 0ull, 0ull};
        unsigned long long accB[4] = {0ull, 0ull, 0ull, 0ull};
#pragma unroll
        for (int kk = 0; kk < 16; kk++) {        // h1@Wh1 + h1@Wx2 (shared loads)
            ulonglong2 pa  = *(const ulonglong2*)(hAr + kk * 8);      // rows 0-3 (bcast)
            ulonglong2 pbv = *(const ulonglong2*)(hAr + kk * 8 + 4);  // rows 4-7 (bcast)
            unsigned long long w1 = dup2(wh1r[kk]);
            fma2(accA[0], pa.x, w1);  fma2(accA[1], pa.y, w1);
            fma2(accA[2], pbv.x, w1); fma2(accA[3], pbv.y, w1);
            unsigned long long w2 = dup2(wx2r[kk]);
            fma2(accB[0], pa.x, w2);  fma2(accB[1], pa.y, w2);
            fma2(accB[2], pbv.x, w2); fma2(accB[3], pbv.y, w2);
        }
#pragma unroll
        for (int kk = 0; kk < 16; kk++) {        // + h2@Wh2
            ulonglong2 pa  = *(const ulonglong2*)(hBr + kk * 8);
            ulonglong2 pbv = *(const ulonglong2*)(hBr + kk * 8 + 4);
            unsigned long long w3 = dup2(wh2r[kk]);
            fma2(accB[0], pa.x, w3);  fma2(accB[1], pa.y, w3);
            fma2(accB[2], pbv.x, w3); fma2(accB[3], pbv.y, w3);
        }

        // Conflict-free swizzled partial store: slot(w,j,lane)=w*128+j*32+(lane^(j<<3))
        {
            const int b4 = w * 128;
            redA[b4 +   0 + (lane      )] = accA[0];
            redA[b4 +  32 + (lane ^  8)] = accA[1];
            redA[b4 +  64 + (lane ^ 16)] = accA[2];
            redA[b4 +  96 + (lane ^ 24)] = accA[3];
            redB[b4 +   0 + (lane      )] = accB[0];
            redB[b4 +  32 + (lane ^  8)] = accB[1];
            redB[b4 +  64 + (lane ^ 16)] = accB[2];
            redB[b4 +  96 + (lane ^ 24)] = accB[3];
        }
        __syncthreads();

        // Reduce 16 partials: sum 8 (own half), shfl-combine with partner lane.
        {
            const unsigned long long* red = s_t ? redB : redA;
            const int ridx = p_e * 32 + (n_e ^ (p_e << 3));
            unsigned long long s = red[(half * 8) * 128 + ridx];
#pragma unroll
            for (int i = 1; i < 8; i++)
                add2(s, red[(half * 8 + i) * 128 + ridx]);
            unsigned plo = __shfl_xor_sync(0xffffffffu, (unsigned)s, 1);
            unsigned phi = __shfl_xor_sync(0xffffffffu, (unsigned)(s >> 32), 1);
            add2(s, ((unsigned long long)phi << 32) | plo);

            if (half == 0) {
                const uint32_t dHA = (q ? OFF_HA0 : OFF_HA1) + soff_full;  // parity q^1
                const uint32_t dHB = (q ? OFF_HB0 : OFF_HB1) + soff_full;
                if (s_t == 0) {
                    if (p < T_) {                     // h1(p+1) -> all 8 peers
                        unsigned long long v = pack2(fast_tanh(lo32(s) + xv0),
                                                     fast_tanh(hi32(s) + xv1));
#pragma unroll
                        for (int r = 0; r < 8; r++) st_cluster_u64(pb[r] + dHA, v);
                    }
                } else {
                    if (p >= 1) {                     // h2(p)
                        float lo = fast_tanh(lo32(s) + bias2);
                        float hi = fast_tanh(hi32(s) + bias2);
                        if (p == T_) {                // final state -> global for head
                            g_h2f[r_off]      = lo;
                            g_h2f[r_off + H_] = hi;
                        } else {
                            unsigned long long v = pack2(lo, hi);
#pragma unroll
                            for (int r = 0; r < 8; r++) st_cluster_u64(pb[r] + dHB, v);
                        }
                    }
                }
            }
        }

        // One fused HW cluster barrier per phase: orders all DSMEM stores and
        // protects red/state buffers for reuse (proven liveness in R10).
        CLUSTER_SYNC();
    }
}

// ============================================================================
// Kernel 3: out = softmax(h2_T @ Wd + bd)   (one CTA per batch row)
// ============================================================================
__global__ void __launch_bounds__(128) head_kernel(const float* __restrict__ Wd,
                                                   const float* __restrict__ bd,
                                                   float* __restrict__ out) {
    __shared__ float h_s[H_];
    __shared__ float red[O_];
    const int b = blockIdx.x, o = threadIdx.x;

    const float* h2 = &g_h2f[b * H_];
    for (int i = o; i < H_; i += O_) h_s[i] = h2[i];
    __syncthreads();

    float acc = bd[o];
#pragma unroll 8
    for (int k = 0; k < H_; k++) acc += h_s[k] * Wd[k * O_ + o];

    red[o] = acc;
    __syncthreads();
    for (int s = 64; s > 0; s >>= 1) {
        if (o < s) red[o] = fmaxf(red[o], red[o + s]);
        __syncthreads();
    }
    const float mx = red[0];
    __syncthreads();
    const float e = expf(acc - mx);
    red[o] = e;
    __syncthreads();
    for (int s = 64; s > 0; s >>= 1) {
        if (o < s) red[o] += red[o + s];
        __syncthreads();
    }
    out[b * O_ + o] = e / red[0];
}

// ============================================================================
extern "C" void kernel_launch(void* const* d_in, const int* in_sizes, int n_in,
                              void* d_out, int out_size) {
    const float* x   = (const float*)d_in[0];
    const float* Wx1 = (const float*)d_in[1];
    const float* Wh1 = (const float*)d_in[2];
    const float* b1  = (const float*)d_in[3];
    const float* Wx2 = (const float*)d_in[4];
    const float* Wh2 = (const float*)d_in[5];
    const float* b2  = (const float*)d_in[6];
    const float* Wd  = (const float*)d_in[7];
    const float* bd  = (const float*)d_in[8];
    float* out = (float*)d_out;

    static bool attr_done = false;
    if (!attr_done) {
        cudaFuncSetAttribute(xproj_kernel,
                             cudaFuncAttributeMaxDynamicSharedMemorySize, 98304);
        cudaFuncSetAttribute(rnn_main_kernel,
                             cudaFuncAttributeMaxDynamicSharedMemorySize, SMEM_REQ);
        attr_done = true;
    }

    xproj_kernel<<<T_, 256, 98304>>>(x, Wx1, b1);
    rnn_main_kernel<<<NCTA, NTHR, SMEM_REQ>>>(Wh1, Wx2, Wh2, b2);  // cluster dims baked
    head_kernel<<<B_, 128>>>(Wd, bd, out);
}

// round 14
// speedup vs baseline: 1.1819x; 1.1819x over previous
#include <cuda_runtime.h>
#include <cstdio>
#include <cstdint>
#include <cstddef>

// Problem constants
#define B_ 128
#define T_ 1024
#define D_ 64
#define H_ 256
#define O_ 128

// 128 CTAs = 16 clusters of 8; cluster = row-group (8 batch rows), rank = col-slice
#define NCTA 128
#define CSZ 8
#define BM 8
#define BN 32
#define NTHR 256   // 8 warps; warp w owns k-chunk [32w, 32w+32)   (R10 proven shape)

// Dynamic-smem byte offsets
#define OFF_HA0  0u          // h1 state parity 0: [256 k][8 m] f32, 8KB
#define OFF_HA1  8192u
#define OFF_HB0  16384u      // h2 state
#define OFF_HB1  24576u
#define OFF_REDA 32768u      // conflict-free reduction scratch, 1024 u64 = 8KB
#define OFF_REDB 40960u
#define SMEM_REQ 102400      // over-request -> 1 CTA/SM guaranteed

// ---------------- device globals (static scratch; no runtime allocation) ----
__device__ float g_xp[(size_t)B_ * T_ * H_];   // Xp[t][b][n] = x@Wx1 + b1
__device__ float g_h2f[B_ * H_];               // final h2(T) for the head

// ---------------- packed f32x2 helpers -------------------------------------
__device__ __forceinline__ void fma2(unsigned long long& acc,
                                     unsigned long long a,
                                     unsigned long long b) {
    asm("fma.rn.f32x2 %0, %1, %2, %0;" : "+l"(acc) : "l"(a), "l"(b));
}
__device__ __forceinline__ void add2(unsigned long long& acc, unsigned long long a) {
    asm("add.rn.f32x2 %0, %0, %1;" : "+l"(acc) : "l"(a));
}
__device__ __forceinline__ unsigned long long dup2(float v) {
    unsigned long long r;
    asm("mov.b64 %0, {%1, %1};" : "=l"(r) : "r"(__float_as_uint(v)));
    return r;
}
__device__ __forceinline__ unsigned long long pack2(float lo, float hi) {
    unsigned long long r;
    asm("mov.b64 %0, {%1, %2};" : "=l"(r) : "r"(__float_as_uint(lo)), "r"(__float_as_uint(hi)));
    return r;
}
__device__ __forceinline__ float lo32(unsigned long long v) {
    return __uint_as_float((unsigned)(v & 0xffffffffull));
}
__device__ __forceinline__ float hi32(unsigned long long v) {
    return __uint_as_float((unsigned)(v >> 32));
}

// ---------------- fast tanh: MUFU ex2 + rcp, ~1e-6 abs error ---------------
__device__ __forceinline__ float fast_tanh(float x) {
    float e, r;
    asm("ex2.approx.f32 %0, %1;" : "=f"(e) : "f"(x * 2.885390081777927f));
    asm("rcp.approx.f32 %0, %1;" : "=f"(r) : "f"(e + 1.0f));
    return fmaf(-2.0f, r, 1.0f);
}

// ---------------- cluster primitives ---------------------------------------
__device__ __forceinline__ uint32_t smem_u32(const void* p) {
    uint32_t a;
    asm("{ .reg .u64 t; cvta.to.shared.u64 t, %1; cvt.u32.u64 %0, t; }" : "=r"(a) : "l"(p));
    return a;
}
__device__ __forceinline__ uint32_t mapa_rank(uint32_t local, uint32_t rank) {
    uint32_t r;
    asm("mapa.shared::cluster.u32 %0, %1, %2;" : "=r"(r) : "r"(local), "r"(rank));
    return r;
}
__device__ __forceinline__ void st_cluster_u64(uint32_t addr, unsigned long long v) {
    asm volatile("st.shared::cluster.u64 [%0], %1;" :: "r"(addr), "l"(v) : "memory");
}
// Fused HW cluster barrier (proven liveness in R10)
#define CLUSTER_SYNC() do { \
    asm volatile("barrier.cluster.arrive.aligned;" ::: "memory"); \
    asm volatile("barrier.cluster.wait.aligned;"   ::: "memory"); } while (0)

// ============================================================================
// Kernel 1: Xp[t][b][:] = x[b][t][:] @ Wx1 + b1   (fully parallel over t)
// ============================================================================
__global__ void __launch_bounds__(256) xproj_kernel(const float* __restrict__ x,
                                                    const float* __restrict__ Wx1,
                                                    const float* __restrict__ b1) {
    extern __shared__ float sm[];
    float* W_s = sm;            // [64][256]  64KB
    float* x_s = sm + D_ * H_;  // [128][64]  32KB
    const int t = blockIdx.x;
    const int tid = threadIdx.x;

    for (int i = tid; i < D_ * H_; i += 256) W_s[i] = Wx1[i];
    for (int i = tid; i < B_ * D_; i += 256) {
        int b = i >> 6, d = i & 63;
        x_s[i] = x[((size_t)b * T_ + t) * D_ + d];
    }
    __syncthreads();

    float wr[D_];
#pragma unroll
    for (int d = 0; d < D_; d++) wr[d] = W_s[d * H_ + tid];
    const float bv = b1[tid];
    float* op = g_xp + (size_t)t * (B_ * H_) + tid;

    for (int b = 0; b < B_; b++) {
        const float4* xr = (const float4*)(x_s + b * D_);
        float a0 = bv, a1 = 0.f, a2 = 0.f, a3 = 0.f;
#pragma unroll
        for (int d4 = 0; d4 < 16; d4 += 4) {
            float4 v0 = xr[d4 + 0], v1 = xr[d4 + 1], v2 = xr[d4 + 2], v3 = xr[d4 + 3];
            a0 += v0.x * wr[4 * d4 + 0]  + v0.y * wr[4 * d4 + 1]
                + v0.z * wr[4 * d4 + 2]  + v0.w * wr[4 * d4 + 3];
            a1 += v1.x * wr[4 * d4 + 4]  + v1.y * wr[4 * d4 + 5]
                + v1.z * wr[4 * d4 + 6]  + v1.w * wr[4 * d4 + 7];
            a2 += v2.x * wr[4 * d4 + 8]  + v2.y * wr[4 * d4 + 9]
                + v2.z * wr[4 * d4 + 10] + v2.w * wr[4 * d4 + 11];
            a3 += v3.x * wr[4 * d4 + 12] + v3.y * wr[4 * d4 + 13]
                + v3.z * wr[4 * d4 + 14] + v3.w * wr[4 * d4 + 15];
        }
        op[(size_t)b * H_] = (a0 + a1) + (a2 + a3);
    }
}

// ============================================================================
// Kernel 2: persistent scan — R10 structure (256 thr, 8 warps, fused
// CLUSTER_SYNC) + conflict-free reduction layout + in-kernel section timers.
// Phase p: h1(p+1) = tanh(Xp[p] + h1(p)@Wh1)            [p < T]
//          h2(p)   = tanh(h1(p)@Wx2 + h2(p-1)@Wh2 + b2) [p >= 1]
// Red layout: slot(j2,w,lane,j&1) = (j2*8 + w)*64 + lane*2 + (j&1)  [u64]
//   writer: per acc-pair one STS.128 at lane*16B within a 512B warp block
//           -> conflict-free;  reader: <=2-way conflicts.
// ============================================================================
__global__ void __launch_bounds__(NTHR, 1) __cluster_dims__(CSZ, 1, 1)
rnn_main_kernel(const float* __restrict__ Wh1,
                const float* __restrict__ Wx2,
                const float* __restrict__ Wh2,
                const float* __restrict__ b2v) {
    extern __shared__ char smem[];
    const uint32_t sbase = smem_u32(smem);
    unsigned long long* redA = (unsigned long long*)(smem + OFF_REDA);
    unsigned long long* redB = (unsigned long long*)(smem + OFF_REDB);

    const int tid = threadIdx.x;
    const int w = tid >> 5, lane = tid & 31;
    uint32_t rank;
    asm("mov.u32 %0, %%cluster_ctarank;" : "=r"(rank));
    const int mi = blockIdx.x >> 3;
    const int m0 = mi * BM, n0 = (int)rank * BN;

    // Weight slices in registers: warp w covers k in [32w, 32w+32)
    float wh1r[32], wx2r[32], wh2r[32];
    {
        const int col = n0 + lane;
#pragma unroll
        for (int kk = 0; kk < 32; kk++) {
            int k = (w << 5) + kk;
            wh1r[kk] = Wh1[k * H_ + col];
            wx2r[kk] = Wx2[k * H_ + col];
            wh2r[kk] = Wh2[k * H_ + col];
        }
    }

    // Zero all four local state buffers (32KB)
    {
        float* s0 = (float*)(smem + OFF_HA0);
        for (int i = tid; i < 8192; i += NTHR) s0[i] = 0.f;
    }

    // Peer smem bases
    uint32_t pb[8];
#pragma unroll
    for (int r = 0; r < 8; r++) pb[r] = mapa_rank(sbase, (uint32_t)r);

    // Epilogue mapping: e in [0,128): rows (m0+2p_e, +1), col n0+n_e
    const int e = tid & 127;
    const int n_e = e >> 2;
    const int p_e = e & 3;
    const int r_off = (m0 + 2 * p_e) * H_ + n0 + n_e;
    const float bias2 = b2v[n0 + n_e];
    const uint32_t soff_full = (uint32_t)((n_e + n0) * 32 + p_e * 8);
    // Reader base into red arrays (u64 index): region (p_e>>1), sub (p_e&1)
    const int rbase = ((p_e >> 1) * 8) * 64 + n_e * 2 + (p_e & 1);

    CLUSTER_SYNC();   // zero-init visible cluster-wide

    // Section timers (per-thread; tid 0 of CTA 0 reports)
    unsigned s_gemm = 0, s_epi = 0, s_sync = 0;

    for (int p = 0; p <= T_; p++) {
        const int q = p & 1;   // input-buffer parity
        unsigned t0 = (unsigned)clock();

        // Prefetch Xp[p] (hides DRAM latency under the GEMM)
        float xv0 = 0.f, xv1 = 0.f;
        if (tid < 128 && p < T_) {
            const float* xpt = g_xp + (size_t)p * (B_ * H_);
            xv0 = __ldcg(xpt + r_off);
            xv1 = __ldcg(xpt + r_off + H_);
        }

        const float* hAr = (const float*)(smem + (q ? OFF_HA1 : OFF_HA0)) + (w << 5) * 8;
        const float* hBr = (const float*)(smem + (q ? OFF_HB1 : OFF_HB0)) + (w << 5) * 8;

        unsigned long long accA[4] = {0ull, 0ull, 0ull, 0ull};
        unsigned long long accB[4] = {0ull, 0ull, 0ull, 0ull};
#pragma unroll
        for (int kk = 0; kk < 32; kk++) {        // h1@Wh1 + h1@Wx2 (shared loads)
            ulonglong2 pa  = *(const ulonglong2*)(hAr + kk * 8);      // rows 0-3 (bcast)
            ulonglong2 pbv = *(const ulonglong2*)(hAr + kk * 8 + 4);  // rows 4-7 (bcast)
            unsigned long long w1 = dup2(wh1r[kk]);
            fma2(accA[0], pa.x, w1);  fma2(accA[1], pa.y, w1);
            fma2(accA[2], pbv.x, w1); fma2(accA[3], pbv.y, w1);
            unsigned long long w2 = dup2(wx2r[kk]);
            fma2(accB[0], pa.x, w2);  fma2(accB[1], pa.y, w2);
            fma2(accB[2], pbv.x, w2); fma2(accB[3], pbv.y, w2);
        }
#pragma unroll
        for (int kk = 0; kk < 32; kk++) {        // + h2@Wh2
            ulonglong2 pa  = *(const ulonglong2*)(hBr + kk * 8);
            ulonglong2 pbv = *(const ulonglong2*)(hBr + kk * 8 + 4);
            unsigned long long w3 = dup2(wh2r[kk]);
            fma2(accB[0], pa.x, w3);  fma2(accB[1], pa.y, w3);
            fma2(accB[2], pbv.x, w3); fma2(accB[3], pbv.y, w3);
        }

        // Conflict-free partial store: STS.128 at lane*16B in 512B warp block
        {
            const int wb0 = (0 * 8 + w) * 64 + lane * 2;   // acc pair {0,1} (rows 0-3)
            const int wb1 = (1 * 8 + w) * 64 + lane * 2;   // acc pair {2,3} (rows 4-7)
            *(ulonglong2*)(redA + wb0) = make_ulonglong2(accA[0], accA[1]);
            *(ulonglong2*)(redA + wb1) = make_ulonglong2(accA[2], accA[3]);
            *(ulonglong2*)(redB + wb0) = make_ulonglong2(accB[0], accB[1]);
            *(ulonglong2*)(redB + wb1) = make_ulonglong2(accB[2], accB[3]);
        }
        __syncthreads();
        unsigned t1 = (unsigned)clock();

        // Reduce 8 warp partials, activate, broadcast to 8 peers' DSMEM.
        {
            const unsigned long long* red = (tid < 128) ? redA : redB;
            unsigned long long s = red[rbase];
#pragma unroll
            for (int w2 = 1; w2 < 8; w2++)
                add2(s, red[rbase + w2 * 64]);

            const uint32_t dHA = (q ? OFF_HA0 : OFF_HA1) + soff_full;  // parity q^1
            const uint32_t dHB = (q ? OFF_HB0 : OFF_HB1) + soff_full;
            if (tid < 128) {
                if (p < T_) {                     // h1(p+1) -> all 8 peers
                    unsigned long long v = pack2(fast_tanh(lo32(s) + xv0),
                                                 fast_tanh(hi32(s) + xv1));
#pragma unroll
                    for (int r = 0; r < 8; r++) st_cluster_u64(pb[r] + dHA, v);
                }
            } else {
                if (p >= 1) {                     // h2(p)
                    float lo = fast_tanh(lo32(s) + bias2);
                    float hi = fast_tanh(hi32(s) + bias2);
                    if (p == T_) {                // final state -> global for head
                        g_h2f[r_off]      = lo;
                        g_h2f[r_off + H_] = hi;
                    } else {
                        unsigned long long v = pack2(lo, hi);
#pragma unroll
                        for (int r = 0; r < 8; r++) st_cluster_u64(pb[r] + dHB, v);
                    }
                }
            }
        }
        unsigned t2 = (unsigned)clock();

        CLUSTER_SYNC();   // orders DSMEM stores + protects buffers for reuse
        unsigned t3 = (unsigned)clock();

        s_gemm += t1 - t0;
        s_epi  += t2 - t1;
        s_sync += t3 - t2;
    }

    // One diagnostic line per launch from one thread on the chip.
    if (blockIdx.x == 0 && tid == 0) {
        printf("RNNPROF gemm=%u epi=%u sync=%u (avg cyc/phase over %d)\n",
               s_gemm / (T_ + 1), s_epi / (T_ + 1), s_sync / (T_ + 1), T_ + 1);
    }
}

// ============================================================================
// Kernel 3: out = softmax(h2_T @ Wd + bd)   (one CTA per batch row)
// ============================================================================
__global__ void __launch_bounds__(128) head_kernel(const float* __restrict__ Wd,
                                                   const float* __restrict__ bd,
                                                   float* __restrict__ out) {
    __shared__ float h_s[H_];
    __shared__ float red[O_];
    const int b = blockIdx.x, o = threadIdx.x;

    const float* h2 = &g_h2f[b * H_];
    for (int i = o; i < H_; i += O_) h_s[i] = h2[i];
    __syncthreads();

    float acc = bd[o];
#pragma unroll 8
    for (int k = 0; k < H_; k++) acc += h_s[k] * Wd[k * O_ + o];

    red[o] = acc;
    __syncthreads();
    for (int s = 64; s > 0; s >>= 1) {
        if (o < s) red[o] = fmaxf(red[o], red[o + s]);
        __syncthreads();
    }
    const float mx = red[0];
    __syncthreads();
    const float e = expf(acc - mx);
    red[o] = e;
    __syncthreads();
    for (int s = 64; s > 0; s >>= 1) {
        if (o < s) red[o] += red[o + s];
        __syncthreads();
    }
    out[b * O_ + o] = e / red[0];
}

// ============================================================================
extern "C" void kernel_launch(void* const* d_in, const int* in_sizes, int n_in,
                              void* d_out, int out_size) {
    const float* x   = (const float*)d_in[0];
    const float* Wx1 = (const float*)d_in[1];
    const float* Wh1 = (const float*)d_in[2];
    const float* b1  = (const float*)d_in[3];
    const float* Wx2 = (const float*)d_in[4];
    const float* Wh2 = (const float*)d_in[5];
    const float* b2  = (const float*)d_in[6];
    const float* Wd  = (const float*)d_in[7];
    const float* bd  = (const float*)d_in[8];
    float* out = (float*)d_out;

    static bool attr_done = false;
    if (!attr_done) {
        cudaFuncSetAttribute(xproj_kernel,
                             cudaFuncAttributeMaxDynamicSharedMemorySize, 98304);
        cudaFuncSetAttribute(rnn_main_kernel,
                             cudaFuncAttributeMaxDynamicSharedMemorySize, SMEM_REQ);
        attr_done = true;
    }

    xproj_kernel<<<T_, 256, 98304>>>(x, Wx1, b1);
    rnn_main_kernel<<<NCTA, NTHR, SMEM_REQ>>>(Wh1, Wx2, Wh2, b2);  // cluster dims baked
    head_kernel<<<B_, 128>>>(Wd, bd, out);
}